// round 13
// baseline (speedup 1.0000x reference)
#include <cuda_runtime.h>
#include <cuda_fp16.h>
#include <cstdint>
#include <math.h>

// ================= problem constants =================
#define Bsz   2
#define CFEAT 128
#define LH    64
#define LW    64
#define NPIX  65536
#define BN_   131072
#define NCELL 8192
#define D1    1024
#define D2    512
#define D3    256
#define D4    128

typedef __half f16;

__device__ __forceinline__ uint32_t smem_to_u32(const void* p) {
    uint32_t a;
    asm("{ .reg .u64 t; cvta.to.shared.u64 t, %1; cvt.u32.u64 %0, t; }" : "=r"(a) : "l"(p));
    return a;
}

// ================= scratch arena =================
#define ALI(x) (((x) + 255) & ~(size_t)255)
static constexpr size_t O_QHR_HI  = 0;
static constexpr size_t O_QHR_LO  = ALI(O_QHR_HI  + (size_t)BN_ * 128 * 2);
static constexpr size_t O_CEL_HI  = ALI(O_QHR_LO  + (size_t)BN_ * 128 * 2);
static constexpr size_t O_CEL_LO  = ALI(O_CEL_HI  + (size_t)NCELL * 256 * 2);
static constexpr size_t O_WHR_F   = ALI(O_CEL_LO  + (size_t)NCELL * 256 * 2);
static constexpr size_t O_WCELL_F = ALI(O_WHR_F   + (size_t)128 * D1 * 4);
static constexpr size_t O_WHRT_H  = ALI(O_WCELL_F + (size_t)256 * D1 * 4);
static constexpr size_t O_WHRT_L  = ALI(O_WHRT_H  + (size_t)D1 * 128 * 2);
static constexpr size_t O_WCT_H   = ALI(O_WHRT_L  + (size_t)D1 * 128 * 2);
static constexpr size_t O_WCT_L   = ALI(O_WCT_H   + (size_t)D1 * 256 * 2);
static constexpr size_t O_W2T_H   = ALI(O_WCT_L   + (size_t)D1 * 256 * 2);
static constexpr size_t O_W2T_L   = ALI(O_W2T_H   + (size_t)D2 * D1 * 2);
static constexpr size_t O_W3T_H   = ALI(O_W2T_L   + (size_t)D2 * D1 * 2);
static constexpr size_t O_W4T_H   = ALI(O_W3T_H   + (size_t)D3 * D2 * 2);
static constexpr size_t O_W4T_L   = ALI(O_W4T_H   + (size_t)D4 * D3 * 2);
static constexpr size_t O_HRTERM  = ALI(O_W4T_L   + (size_t)D4 * D3 * 2);   // f16
static constexpr size_t O_CCELL   = ALI(O_HRTERM  + (size_t)BN_ * D1 * 2);  // f16
static constexpr size_t O_X1      = ALI(O_CCELL   + (size_t)NCELL * D1 * 2);            // 2 corners
static constexpr size_t O_H2      = ALI(O_X1      + (size_t)2 * BN_ * D1 * 2);
static constexpr size_t O_H3      = ALI(O_H2      + (size_t)2 * BN_ * D2 * 2);
static constexpr size_t O_H4      = ALI(O_H3      + (size_t)2 * BN_ * D3 * 2);
static constexpr size_t SCRATCH_BYTES = ALI(O_H4 + (size_t)4 * BN_ * D4 * 4);

__device__ unsigned char g_scratch[SCRATCH_BYTES];   // ~1.5 GB

__device__ __forceinline__ void split_f16(float v, unsigned short& h, unsigned short& l) {
    __half hh = __float2half_rn(v);
    float r = v - __half2float(hh);
    __half ll = __float2half_rn(r);
    h = *(unsigned short*)&hh;
    l = *(unsigned short*)&ll;
}

// ================= transpose + split (channel->pixel), fp16 hi/lo =================
__global__ void k_tsplit(const float* __restrict__ in, f16* __restrict__ ohi, f16* __restrict__ olo,
                         int P, int ldo, int co, float scale, size_t inBS, size_t outBS)
{
    __shared__ float tile[32][33];
    const float* inb = in + blockIdx.z * inBS;
    int p0 = blockIdx.x * 32, c0 = blockIdx.y * 32;
    int tx = threadIdx.x, ty = threadIdx.y;   // (32,8)
#pragma unroll
    for (int r = 0; r < 32; r += 8)
        tile[ty + r][tx] = inb[(size_t)(c0 + ty + r) * P + p0 + tx];
    __syncthreads();
#pragma unroll
    for (int r = 0; r < 32; r += 8) {
        float v = tile[tx][ty + r] * scale;
        unsigned short h, l; split_f16(v, h, l);
        size_t o = blockIdx.z * outBS + (size_t)(p0 + ty + r) * ldo + co + c0 + tx;
        *(unsigned short*)&ohi[o] = h;
        *(unsigned short*)&olo[o] = l;
    }
}

// ================= build factored layer-1 weights =================
__global__ void k_prepw(const float* __restrict__ w1, float* __restrict__ whr, float* __restrict__ wcell)
{
    int t = blockIdx.x * blockDim.x + threadIdx.x;
    if (t >= 384 * D1) return;
    int r = t >> 10, c = t & 1023;
    if (r < 128)
        whr[t] = w1[(size_t)(128 + r) * D1 + c] + w1[(size_t)(256 + r) * D1 + c];
    if (r < 256) {
        int src = (r < 128) ? r : (128 + r);
        wcell[t] = w1[(size_t)src * D1 + c];
    }
}

// ================= weight transpose + split: W[K,N] -> T hi/lo [N,K], fp16 =================
__global__ void k_wsplit(const float* __restrict__ w, f16* __restrict__ thi, f16* __restrict__ tlo,
                         int K, int N)
{
    __shared__ float tile[32][33];
    int n0 = blockIdx.x * 32, k0 = blockIdx.y * 32;
    int tx = threadIdx.x, ty = threadIdx.y;
#pragma unroll
    for (int r = 0; r < 32; r += 8)
        tile[ty + r][tx] = w[(size_t)(k0 + ty + r) * N + n0 + tx];
    __syncthreads();
#pragma unroll
    for (int r = 0; r < 32; r += 8) {
        float v = tile[tx][ty + r];
        unsigned short h, l; split_f16(v, h, l);
        size_t o = (size_t)(n0 + ty + r) * K + k0 + tx;
        *(unsigned short*)&thi[o] = h;
        if (tlo) *(unsigned short*)&tlo[o] = l;
    }
}

// ================= mma.sync fp16 split GEMM, BK=64 =================
// 128x128 tile, BK=64, 8 warps (2x4), warp tile 64x32, 2-stage double buffer.
// NT=3: Ah*Bh + Ah*Bl + Al*Bh (4 tiles; occ 1) / NT=2 (3 tiles; occ 2) / NT=1 (2 tiles; occ 2)
// Tile order in stage: [AH][BH][BL][AL].  Pitch 144B: row stride = 4 banks -> 8-row
// ldmatrix groups hit all 32 banks; conflict-free.
#define TILE_PITCH 144                 // 128B data + 16B pad
#define TILE_BYTES (128 * TILE_PITCH)  // 18432

__device__ __forceinline__ void ldsm4(uint32_t* r, uint32_t addr) {
    asm volatile("ldmatrix.sync.aligned.m8n8.x4.shared.b16 {%0,%1,%2,%3}, [%4];"
                 : "=r"(r[0]), "=r"(r[1]), "=r"(r[2]), "=r"(r[3]) : "r"(addr));
}
__device__ __forceinline__ void mma16816(float* c, const uint32_t* a, uint32_t b0, uint32_t b1) {
    asm volatile("mma.sync.aligned.m16n8k16.row.col.f32.f16.f16.f32 "
                 "{%0,%1,%2,%3}, {%4,%5,%6,%7}, {%8,%9}, {%0,%1,%2,%3};"
                 : "+f"(c[0]), "+f"(c[1]), "+f"(c[2]), "+f"(c[3])
                 : "r"(a[0]), "r"(a[1]), "r"(a[2]), "r"(a[3]), "r"(b0), "r"(b1));
}
#define CP16(dst, src) \
    asm volatile("cp.async.cg.shared.global [%0], [%1], 16;" :: "r"(dst), "l"(src))

template<int NT>
__global__ __launch_bounds__(256, (NT == 3 ? 1 : 2))
void k_gemm(const f16* __restrict__ Ahi, const f16* __restrict__ Alo,
            const f16* __restrict__ Bhi, const f16* __restrict__ Blo,
            const float* __restrict__ bias,
            float* __restrict__ Cfp, f16* __restrict__ Chf,
            int N, int K, int relu)
{
    constexpr int NTILES = NT + 1;
    constexpr uint32_t STAGE = NTILES * TILE_BYTES;
    extern __shared__ char smem[];
    const int tid = threadIdx.x;
    const int wid = tid >> 5, lane = tid & 31;
    const int wr = wid >> 2, wc = wid & 3;
    const size_t m0 = (size_t)blockIdx.y * 128;
    const size_t n0 = (size_t)blockIdx.x * 128;
    const uint32_t sbase = smem_to_u32(smem);

    // loader: 256 threads; per tile: rows lrow,+64 x two 64B halves
    const int lrow = tid >> 2;      // 0..63
    const int lch  = tid & 3;       // 16B chunk within first 64B
    const f16* gAh = Ahi + (m0 + lrow) * K + lch * 8;
    const f16* gAl = (NT == 3) ? (Alo + (m0 + lrow) * K + lch * 8) : gAh;
    const f16* gBh = Bhi + (n0 + lrow) * K + lch * 8;
    const f16* gBl = (NT >= 2) ? (Blo + (n0 + lrow) * K + lch * 8) : gBh;
    const size_t rstep = (size_t)64 * K;   // 64 rows
    const uint32_t sRow = lrow * TILE_PITCH + lch * 16;

    auto load_stage = [&](int s, int k0) {
        uint32_t sb_ = sbase + s * STAGE + sRow;
#pragma unroll
        for (int p = 0; p < 2; p++) {          // row halves 0..63 / 64..127
#pragma unroll
            for (int q = 0; q < 2; q++) {      // 64B halves of the 128B row
                uint32_t d_ = sb_ + p * 64 * TILE_PITCH + q * 64;
                size_t  g_ = (size_t)k0 + p * rstep + q * 32;
                CP16(d_,                  gAh + g_);
                CP16(d_ + 1 * TILE_BYTES, gBh + g_);
                if (NT >= 2) CP16(d_ + 2 * TILE_BYTES, gBl + g_);
                if (NT == 3) CP16(d_ + 3 * TILE_BYTES, gAl + g_);
            }
        }
        asm volatile("cp.async.commit_group;");
    };

    const uint32_t aOff = (wr * 64 + (lane & 15)) * TILE_PITCH + ((lane >> 4) << 4);
    const uint32_t bOff = (wc * 32 + (lane & 7) + ((lane >> 4) << 3)) * TILE_PITCH
                        + (((lane >> 3) & 1) << 4);

    float acc[4][4][4];
#pragma unroll
    for (int i = 0; i < 4; i++)
#pragma unroll
        for (int j = 0; j < 4; j++)
#pragma unroll
            for (int k = 0; k < 4; k++) acc[i][j][k] = 0.f;

    const int nch = K >> 6;          // BK=64; >= 2 for all layers
    load_stage(0, 0);
    load_stage(1, 64);

    for (int ch = 0; ch < nch; ch++) {
        if (ch + 1 < nch) asm volatile("cp.async.wait_group 1;");
        else              asm volatile("cp.async.wait_group 0;");
        __syncthreads();

        const int st = ch & 1;
        const uint32_t stA = sbase + st * STAGE;
#pragma unroll
        for (int ks = 0; ks < 4; ks++) {       // 4 x 16-K steps
            uint32_t aH[4][4], aL[4][4], bH[2][4], bL[2][4];
#pragma unroll
            for (int mt = 0; mt < 4; mt++) {
                uint32_t ad = stA + aOff + mt * (16 * TILE_PITCH) + ks * 32;
                ldsm4(aH[mt], ad);
                if (NT == 3) ldsm4(aL[mt], ad + 3 * TILE_BYTES);
            }
#pragma unroll
            for (int np = 0; np < 2; np++) {
                uint32_t bd = stA + 1 * TILE_BYTES + bOff + np * (16 * TILE_PITCH) + ks * 32;
                ldsm4(bH[np], bd);
                if (NT >= 2) ldsm4(bL[np], bd + TILE_BYTES);
            }
#pragma unroll
            for (int mt = 0; mt < 4; mt++)
#pragma unroll
                for (int nt = 0; nt < 4; nt++) {
                    int np = nt >> 1, j = (nt & 1) * 2;
                    mma16816(acc[mt][nt], aH[mt], bH[np][j], bH[np][j + 1]);
                }
            if (NT >= 2) {
#pragma unroll
                for (int mt = 0; mt < 4; mt++)
#pragma unroll
                    for (int nt = 0; nt < 4; nt++) {
                        int np = nt >> 1, j = (nt & 1) * 2;
                        mma16816(acc[mt][nt], aH[mt], bL[np][j], bL[np][j + 1]);
                    }
            }
            if (NT == 3) {
#pragma unroll
                for (int mt = 0; mt < 4; mt++)
#pragma unroll
                    for (int nt = 0; nt < 4; nt++) {
                        int np = nt >> 1, j = (nt & 1) * 2;
                        mma16816(acc[mt][nt], aL[mt], bH[np][j], bH[np][j + 1]);
                    }
            }
        }
        __syncthreads();
        if (ch + 2 < nch) load_stage(st, (ch + 2) * 64);
    }

    // ---- epilogue ----
#pragma unroll
    for (int mt = 0; mt < 4; mt++) {
#pragma unroll
        for (int nt = 0; nt < 4; nt++) {
            size_t row = m0 + wr * 64 + mt * 16 + (lane >> 2);
            int col = (int)n0 + wc * 32 + nt * 8 + (lane & 3) * 2;
            float b0 = bias ? __ldg(&bias[col])     : 0.f;
            float b1 = bias ? __ldg(&bias[col + 1]) : 0.f;
            float v00 = acc[mt][nt][0] + b0, v01 = acc[mt][nt][1] + b1;
            float v10 = acc[mt][nt][2] + b0, v11 = acc[mt][nt][3] + b1;
            if (relu) {
                v00 = fmaxf(v00, 0.f); v01 = fmaxf(v01, 0.f);
                v10 = fmaxf(v10, 0.f); v11 = fmaxf(v11, 0.f);
            }
            if (Cfp) {
                *(float2*)&Cfp[row * N + col]       = make_float2(v00, v01);
                *(float2*)&Cfp[(row + 8) * N + col] = make_float2(v10, v11);
            } else {
                __half2 p0 = __floats2half2_rn(v00, v01);
                __half2 p1 = __floats2half2_rn(v10, v11);
                *(uint32_t*)&Chf[row * N + col]       = *(uint32_t*)&p0;
                *(uint32_t*)&Chf[(row + 8) * N + col] = *(uint32_t*)&p1;
            }
        }
    }
}

// ================= assemble x1 for a PAIR of corners (reads hrterm once) =================
__global__ __launch_bounds__(256)
void k_asm2(const float* __restrict__ coord, const f16* __restrict__ hrterm,
            const f16* __restrict__ ccell, const float* __restrict__ w1,
            f16* __restrict__ x1, int pair)
{
    int bn = blockIdx.x;
    int b = bn >> 16;
    float cy0 = coord[(size_t)bn * 2 + 0];
    float cx0 = coord[(size_t)bn * 2 + 1];

    int c = threadIdx.x * 4;
    uint2 hraw = *(const uint2*)&hrterm[(size_t)bn * D1 + c];
    __half2 h01 = *(__half2*)&hraw.x, h23 = *(__half2*)&hraw.y;
    float4 h = make_float4(__low2float(h01), __high2float(h01),
                           __low2float(h23), __high2float(h23));
    float4 w0 = *(const float4*)&w1[(size_t)384 * D1 + c];
    float4 w8 = *(const float4*)&w1[(size_t)385 * D1 + c];

#pragma unroll
    for (int sub = 0; sub < 2; sub++) {
        int corner = pair * 2 + sub;
        float vx = (corner & 2) ? 1.f : -1.f;
        float vy = (corner & 1) ? 1.f : -1.f;
        float cy = cy0 + vx * (1.f / 64.f);
        float cx = cx0 + vy * (1.f / 64.f);
        int iy = (int)floorf((cy + 1.f) * 32.f);
        int ix = (int)floorf((cx + 1.f) * 32.f);
        bool valid = (iy >= 0) & (iy < LH) & (ix >= 0) & (ix < LW);
        float qy = valid ? (-1.f + (float)(2 * iy + 1) * (1.f / 64.f)) : 0.f;
        float qx = valid ? (-1.f + (float)(2 * ix + 1) * (1.f / 64.f)) : 0.f;
        float rely = (cy0 - qy) * 64.f;
        float relx = (cx0 - qx) * 64.f;

        float4 v;
        v.x = h.x + rely * w0.x + relx * w8.x;
        v.y = h.y + rely * w0.y + relx * w8.y;
        v.z = h.z + rely * w0.z + relx * w8.z;
        v.w = h.w + rely * w0.w + relx * w8.w;
        if (valid) {
            uint2 craw = *(const uint2*)&ccell[(size_t)(b * 4096 + iy * LW + ix) * D1 + c];
            __half2 c01 = *(__half2*)&craw.x, c23 = *(__half2*)&craw.y;
            v.x += __low2float(c01); v.y += __high2float(c01);
            v.z += __low2float(c23); v.w += __high2float(c23);
        }
        __half2 p0 = __floats2half2_rn(fmaxf(v.x, 0.f), fmaxf(v.y, 0.f));
        __half2 p1 = __floats2half2_rn(fmaxf(v.z, 0.f), fmaxf(v.w, 0.f));
        uint2 pk; pk.x = *(uint32_t*)&p0; pk.y = *(uint32_t*)&p1;
        *(uint2*)&x1[(size_t)(sub * BN_ + bn) * D1 + c] = pk;
    }
}

// ================= layer-5 + softmax reduce =================
__global__ __launch_bounds__(256)
void k_out(const float* __restrict__ h4, const float* __restrict__ w5,
           const float* __restrict__ b5, float* __restrict__ out)
{
    int gw = (blockIdx.x * blockDim.x + threadIdx.x) >> 5;
    int lane = threadIdx.x & 31;
    if (gw >= BN_) return;

    float pe[4], pw[4];
#pragma unroll
    for (int cnr = 0; cnr < 4; cnr++) {
        const float* h = h4 + (size_t)(cnr * BN_ + gw) * D4;
        float4 v = *(const float4*)&h[lane * 4];
        int k = lane * 4;
        float s0 = v.x * w5[(k+0)*2+0] + v.y * w5[(k+1)*2+0] + v.z * w5[(k+2)*2+0] + v.w * w5[(k+3)*2+0];
        float s1 = v.x * w5[(k+0)*2+1] + v.y * w5[(k+1)*2+1] + v.z * w5[(k+2)*2+1] + v.w * w5[(k+3)*2+1];
#pragma unroll
        for (int o = 16; o; o >>= 1) {
            s0 += __shfl_xor_sync(0xffffffffu, s0, o);
            s1 += __shfl_xor_sync(0xffffffffu, s1, o);
        }
        pe[cnr] = s0 + b5[0];
        pw[cnr] = s1 + b5[1];
    }
    if (lane == 0) {
        float m = fmaxf(fmaxf(pw[0], pw[1]), fmaxf(pw[2], pw[3]));
        float e0 = expf(pw[0] - m), e1 = expf(pw[1] - m);
        float e2 = expf(pw[2] - m), e3 = expf(pw[3] - m);
        float se = e0 + e1 + e2 + e3;
        out[gw] = (pe[0]*e0 + pe[1]*e1 + pe[2]*e2 + pe[3]*e3) / se;
    }
}

// ================= launch =================
extern "C" void kernel_launch(void* const* d_in, const int* in_sizes, int n_in,
                              void* d_out, int out_size)
{
    const float* feat  = (const float*)d_in[0];
    const float* coord = (const float*)d_in[1];
    const float* hrg   = (const float*)d_in[2];
    const float* lrg   = (const float*)d_in[3];
    const float* w1 = (const float*)d_in[4];  const float* b1 = (const float*)d_in[5];
    const float* w2 = (const float*)d_in[6];  const float* b2 = (const float*)d_in[7];
    const float* w3 = (const float*)d_in[8];  const float* b3 = (const float*)d_in[9];
    const float* w4 = (const float*)d_in[10]; const float* b4 = (const float*)d_in[11];
    const float* w5 = (const float*)d_in[12]; const float* b5 = (const float*)d_in[13];
    float* out = (float*)d_out;

    unsigned char* S;
    cudaGetSymbolAddress((void**)&S, g_scratch);
    f16*   qhrH  = (f16*)(S + O_QHR_HI);   f16* qhrL  = (f16*)(S + O_QHR_LO);
    f16*   celH  = (f16*)(S + O_CEL_HI);   f16* celL  = (f16*)(S + O_CEL_LO);
    float* whrF  = (float*)(S + O_WHR_F);  float* wcellF = (float*)(S + O_WCELL_F);
    f16*   whrtH = (f16*)(S + O_WHRT_H);   f16* whrtL = (f16*)(S + O_WHRT_L);
    f16*   wctH  = (f16*)(S + O_WCT_H);    f16* wctL  = (f16*)(S + O_WCT_L);
    f16*   w2tH  = (f16*)(S + O_W2T_H);    f16* w2tL  = (f16*)(S + O_W2T_L);
    f16*   w3tH  = (f16*)(S + O_W3T_H);
    f16*   w4tH  = (f16*)(S + O_W4T_H);    f16* w4tL  = (f16*)(S + O_W4T_L);
    f16*   hrterm = (f16*)(S + O_HRTERM);
    f16*   ccell  = (f16*)(S + O_CCELL);
    f16*   x1 = (f16*)(S + O_X1);
    f16*   h2 = (f16*)(S + O_H2);
    f16*   h3 = (f16*)(S + O_H3);
    float* h4 = (float*)(S + O_H4);

    const int SMEM3 = 2 * 4 * TILE_BYTES;   // 147456 (occ 1)
    const int SMEM2 = 2 * 3 * TILE_BYTES;   // 110592 (x2 CTAs = 221KB/SM)
    const int SMEM1 = 2 * 2 * TILE_BYTES;   // 73728  (x2 CTAs = 147KB/SM)
    cudaFuncSetAttribute(k_gemm<3>, cudaFuncAttributeMaxDynamicSharedMemorySize, SMEM3);
    cudaFuncSetAttribute(k_gemm<2>, cudaFuncAttributeMaxDynamicSharedMemorySize, SMEM2);
    cudaFuncSetAttribute(k_gemm<1>, cudaFuncAttributeMaxDynamicSharedMemorySize, SMEM1);

    dim3 t32x8(32, 8);
    k_tsplit<<<dim3(NPIX/32, CFEAT/32, Bsz), t32x8>>>(hrg, qhrH, qhrL, NPIX, 128, 0, 1.f,
        (size_t)CFEAT * NPIX, (size_t)NPIX * 128);
    k_tsplit<<<dim3(4096/32, CFEAT/32, Bsz), t32x8>>>(feat, celH, celL, 4096, 256, 0, 1.f,
        (size_t)CFEAT * 4096, (size_t)4096 * 256);
    k_tsplit<<<dim3(4096/32, CFEAT/32, Bsz), t32x8>>>(lrg, celH, celL, 4096, 256, 128, -1.f,
        (size_t)CFEAT * 4096, (size_t)4096 * 256);
    k_prepw<<<(384 * D1 + 255) / 256, 256>>>(w1, whrF, wcellF);
    k_wsplit<<<dim3(D1/32, 128/32), t32x8>>>(whrF,   whrtH, whrtL, 128, D1);
    k_wsplit<<<dim3(D1/32, 256/32), t32x8>>>(wcellF, wctH,  wctL,  256, D1);
    k_wsplit<<<dim3(D2/32, D1/32),  t32x8>>>(w2, w2tH, w2tL, D1, D2);
    k_wsplit<<<dim3(D3/32, D2/32),  t32x8>>>(w3, w3tH, nullptr, D2, D3);
    k_wsplit<<<dim3(D4/32, D3/32),  t32x8>>>(w4, w4tH, w4tL, D3, D4);

    // HR term: [131072,128]@[128,1024] + b1 -> f16 (3-term)
    k_gemm<3><<<dim3(D1/128, BN_/128), 256, SMEM3>>>(qhrH, qhrL, whrtH, whrtL, b1,
        nullptr, hrterm, D1, 128, 0);
    // cell term: [8192,256]@[256,1024] -> f16 (3-term)
    k_gemm<3><<<dim3(D1/128, NCELL/128), 256, SMEM3>>>(celH, celL, wctH, wctL, nullptr,
        nullptr, ccell, D1, 256, 0);

    const int M2 = 2 * BN_;   // two corners per chain
    for (int pair = 0; pair < 2; pair++) {
        k_asm2<<<BN_, 256>>>(coord, hrterm, ccell, w1, x1, pair);
        k_gemm<2><<<dim3(D2/128, M2/128), 256, SMEM2>>>(x1, nullptr, w2tH, w2tL, b2,
            nullptr, h2, D2, D1, 1);
        k_gemm<1><<<dim3(D3/128, M2/128), 256, SMEM1>>>(h2, nullptr, w3tH, nullptr, b3,
            nullptr, h3, D3, D2, 1);
        k_gemm<2><<<dim3(D4/128, M2/128), 256, SMEM2>>>(h3, nullptr, w4tH, w4tL, b4,
            h4 + (size_t)pair * 2 * BN_ * D4, nullptr, D4, D3, 1);
    }

    k_out<<<(BN_ * 32) / 256, 256>>>(h4, w5, b5, out);
}

// round 14
// speedup vs baseline: 1.2326x; 1.2326x over previous
#include <cuda_runtime.h>
#include <cuda_fp16.h>
#include <cstdint>
#include <math.h>

// ================= problem constants =================
#define Bsz   2
#define CFEAT 128
#define LH    64
#define LW    64
#define NPIX  65536
#define BN_   131072
#define NCELL 8192
#define D1    1024
#define D2    512
#define D3    256
#define D4    128

typedef __half f16;

__device__ __forceinline__ uint32_t smem_to_u32(const void* p) {
    uint32_t a;
    asm("{ .reg .u64 t; cvta.to.shared.u64 t, %1; cvt.u32.u64 %0, t; }" : "=r"(a) : "l"(p));
    return a;
}

// ================= scratch arena =================
#define ALI(x) (((x) + 255) & ~(size_t)255)
static constexpr size_t O_QHR_HI  = 0;
static constexpr size_t O_QHR_LO  = ALI(O_QHR_HI  + (size_t)BN_ * 128 * 2);
static constexpr size_t O_CEL_HI  = ALI(O_QHR_LO  + (size_t)BN_ * 128 * 2);
static constexpr size_t O_CEL_LO  = ALI(O_CEL_HI  + (size_t)NCELL * 256 * 2);
static constexpr size_t O_WHR_F   = ALI(O_CEL_LO  + (size_t)NCELL * 256 * 2);
static constexpr size_t O_WCELL_F = ALI(O_WHR_F   + (size_t)128 * D1 * 4);
static constexpr size_t O_WHRT_H  = ALI(O_WCELL_F + (size_t)256 * D1 * 4);
static constexpr size_t O_WHRT_L  = ALI(O_WHRT_H  + (size_t)D1 * 128 * 2);
static constexpr size_t O_WCT_H   = ALI(O_WHRT_L  + (size_t)D1 * 128 * 2);
static constexpr size_t O_WCT_L   = ALI(O_WCT_H   + (size_t)D1 * 256 * 2);
static constexpr size_t O_W2T_H   = ALI(O_WCT_L   + (size_t)D1 * 256 * 2);
static constexpr size_t O_W3T_H   = ALI(O_W2T_H   + (size_t)D2 * D1 * 2);
static constexpr size_t O_W3T_L   = ALI(O_W3T_H   + (size_t)D3 * D2 * 2);
static constexpr size_t O_W4T_H   = ALI(O_W3T_L   + (size_t)D3 * D2 * 2);
static constexpr size_t O_W4T_L   = ALI(O_W4T_H   + (size_t)D4 * D3 * 2);
static constexpr size_t O_HRTERM  = ALI(O_W4T_L   + (size_t)D4 * D3 * 2);   // f16
static constexpr size_t O_CCELL   = ALI(O_HRTERM  + (size_t)BN_ * D1 * 2);  // f16
static constexpr size_t O_X1      = ALI(O_CCELL   + (size_t)NCELL * D1 * 2);            // 2 corners
static constexpr size_t O_H2      = ALI(O_X1      + (size_t)2 * BN_ * D1 * 2);
static constexpr size_t O_H3      = ALI(O_H2      + (size_t)2 * BN_ * D2 * 2);
static constexpr size_t O_H4      = ALI(O_H3      + (size_t)2 * BN_ * D3 * 2);
static constexpr size_t SCRATCH_BYTES = ALI(O_H4 + (size_t)4 * BN_ * D4 * 4);

__device__ unsigned char g_scratch[SCRATCH_BYTES];   // ~1.5 GB

__device__ __forceinline__ void split_f16(float v, unsigned short& h, unsigned short& l) {
    __half hh = __float2half_rn(v);
    float r = v - __half2float(hh);
    __half ll = __float2half_rn(r);
    h = *(unsigned short*)&hh;
    l = *(unsigned short*)&ll;
}

// ================= transpose + split (channel->pixel), fp16 hi/lo =================
__global__ void k_tsplit(const float* __restrict__ in, f16* __restrict__ ohi, f16* __restrict__ olo,
                         int P, int ldo, int co, float scale, size_t inBS, size_t outBS)
{
    __shared__ float tile[32][33];
    const float* inb = in + blockIdx.z * inBS;
    int p0 = blockIdx.x * 32, c0 = blockIdx.y * 32;
    int tx = threadIdx.x, ty = threadIdx.y;   // (32,8)
#pragma unroll
    for (int r = 0; r < 32; r += 8)
        tile[ty + r][tx] = inb[(size_t)(c0 + ty + r) * P + p0 + tx];
    __syncthreads();
#pragma unroll
    for (int r = 0; r < 32; r += 8) {
        float v = tile[tx][ty + r] * scale;
        unsigned short h, l; split_f16(v, h, l);
        size_t o = blockIdx.z * outBS + (size_t)(p0 + ty + r) * ldo + co + c0 + tx;
        *(unsigned short*)&ohi[o] = h;
        *(unsigned short*)&olo[o] = l;
    }
}

// ================= build factored layer-1 weights =================
__global__ void k_prepw(const float* __restrict__ w1, float* __restrict__ whr, float* __restrict__ wcell)
{
    int t = blockIdx.x * blockDim.x + threadIdx.x;
    if (t >= 384 * D1) return;
    int r = t >> 10, c = t & 1023;
    if (r < 128)
        whr[t] = w1[(size_t)(128 + r) * D1 + c] + w1[(size_t)(256 + r) * D1 + c];
    if (r < 256) {
        int src = (r < 128) ? r : (128 + r);
        wcell[t] = w1[(size_t)src * D1 + c];
    }
}

// ================= weight transpose + split: W[K,N] -> T hi/lo [N,K], fp16 =================
__global__ void k_wsplit(const float* __restrict__ w, f16* __restrict__ thi, f16* __restrict__ tlo,
                         int K, int N)
{
    __shared__ float tile[32][33];
    int n0 = blockIdx.x * 32, k0 = blockIdx.y * 32;
    int tx = threadIdx.x, ty = threadIdx.y;
#pragma unroll
    for (int r = 0; r < 32; r += 8)
        tile[ty + r][tx] = w[(size_t)(k0 + ty + r) * N + n0 + tx];
    __syncthreads();
#pragma unroll
    for (int r = 0; r < 32; r += 8) {
        float v = tile[tx][ty + r];
        unsigned short h, l; split_f16(v, h, l);
        size_t o = (size_t)(n0 + ty + r) * K + k0 + tx;
        *(unsigned short*)&thi[o] = h;
        if (tlo) *(unsigned short*)&tlo[o] = l;
    }
}

// ================= mma.sync fp16 split GEMM (BK=32, round-12 engine) =================
// 128x128 tile, BK=32, 8 warps (2x4), warp tile 64x32, 2-stage double buffer.
// NT=3: Ah*Bh + Ah*Bl + Al*Bh (4 tiles; occ 1) / NT=2: Ah*Bh + Ah*Bl (3 tiles; occ 2)
// NT=1: Ah*Bh (2 tiles; occ 2). Tile order in stage: [AH][BH][BL][AL]
#define TILE_PITCH 80
#define TILE_BYTES (128 * TILE_PITCH)

__device__ __forceinline__ void ldsm4(uint32_t* r, uint32_t addr) {
    asm volatile("ldmatrix.sync.aligned.m8n8.x4.shared.b16 {%0,%1,%2,%3}, [%4];"
                 : "=r"(r[0]), "=r"(r[1]), "=r"(r[2]), "=r"(r[3]) : "r"(addr));
}
__device__ __forceinline__ void mma16816(float* c, const uint32_t* a, uint32_t b0, uint32_t b1) {
    asm volatile("mma.sync.aligned.m16n8k16.row.col.f32.f16.f16.f32 "
                 "{%0,%1,%2,%3}, {%4,%5,%6,%7}, {%8,%9}, {%0,%1,%2,%3};"
                 : "+f"(c[0]), "+f"(c[1]), "+f"(c[2]), "+f"(c[3])
                 : "r"(a[0]), "r"(a[1]), "r"(a[2]), "r"(a[3]), "r"(b0), "r"(b1));
}
#define CP16(dst, src) \
    asm volatile("cp.async.cg.shared.global [%0], [%1], 16;" :: "r"(dst), "l"(src))

template<int NT>
__global__ __launch_bounds__(256, (NT == 3 ? 1 : 2))
void k_gemm(const f16* __restrict__ Ahi, const f16* __restrict__ Alo,
            const f16* __restrict__ Bhi, const f16* __restrict__ Blo,
            const float* __restrict__ bias,
            float* __restrict__ Cfp, f16* __restrict__ Chf,
            int N, int K, int relu)
{
    constexpr int NTILES = NT + 1;
    constexpr uint32_t STAGE = NTILES * TILE_BYTES;
    extern __shared__ char smem[];
    const int tid = threadIdx.x;
    const int wid = tid >> 5, lane = tid & 31;
    const int wr = wid >> 2, wc = wid & 3;
    const size_t m0 = (size_t)blockIdx.y * 128;
    const size_t n0 = (size_t)blockIdx.x * 128;
    const uint32_t sbase = smem_to_u32(smem);

    const int lrow = tid >> 2;
    const int lch  = tid & 3;
    const f16* gAh = Ahi + (m0 + lrow) * K + lch * 8;
    const f16* gAl = (NT == 3) ? (Alo + (m0 + lrow) * K + lch * 8) : gAh;
    const f16* gBh = Bhi + (n0 + lrow) * K + lch * 8;
    const f16* gBl = (NT >= 2) ? (Blo + (n0 + lrow) * K + lch * 8) : gBh;
    const size_t rstep = (size_t)64 * K;
    const uint32_t sRow = lrow * TILE_PITCH + lch * 16;

    auto load_stage = [&](int s, int k0) {
        uint32_t sb_ = sbase + s * STAGE + sRow;
#pragma unroll
        for (int p = 0; p < 2; p++) {
            uint32_t d_ = sb_ + p * 64 * TILE_PITCH;
            CP16(d_,                  gAh + k0 + p * rstep);
            CP16(d_ + 1 * TILE_BYTES, gBh + k0 + p * rstep);
            if (NT >= 2) CP16(d_ + 2 * TILE_BYTES, gBl + k0 + p * rstep);
            if (NT == 3) CP16(d_ + 3 * TILE_BYTES, gAl + k0 + p * rstep);
        }
        asm volatile("cp.async.commit_group;");
    };

    const uint32_t aOff = (wr * 64 + (lane & 15)) * TILE_PITCH + ((lane >> 4) << 4);
    const uint32_t bOff = (wc * 32 + (lane & 7) + ((lane >> 4) << 3)) * TILE_PITCH
                        + (((lane >> 3) & 1) << 4);

    float acc[4][4][4];
#pragma unroll
    for (int i = 0; i < 4; i++)
#pragma unroll
        for (int j = 0; j < 4; j++)
#pragma unroll
            for (int k = 0; k < 4; k++) acc[i][j][k] = 0.f;

    const int nch = K >> 5;
    load_stage(0, 0);
    load_stage(1, 32);

    for (int ch = 0; ch < nch; ch++) {
        if (ch + 1 < nch) asm volatile("cp.async.wait_group 1;");
        else              asm volatile("cp.async.wait_group 0;");
        __syncthreads();

        const int st = ch & 1;
        const uint32_t stA = sbase + st * STAGE;
#pragma unroll
        for (int ks = 0; ks < 2; ks++) {
            uint32_t aH[4][4], aL[4][4], bH[2][4], bL[2][4];
#pragma unroll
            for (int mt = 0; mt < 4; mt++) {
                uint32_t ad = stA + aOff + mt * (16 * TILE_PITCH) + ks * 32;
                ldsm4(aH[mt], ad);
                if (NT == 3) ldsm4(aL[mt], ad + 3 * TILE_BYTES);
            }
#pragma unroll
            for (int np = 0; np < 2; np++) {
                uint32_t bd = stA + 1 * TILE_BYTES + bOff + np * (16 * TILE_PITCH) + ks * 32;
                ldsm4(bH[np], bd);
                if (NT >= 2) ldsm4(bL[np], bd + TILE_BYTES);
            }
#pragma unroll
            for (int mt = 0; mt < 4; mt++)
#pragma unroll
                for (int nt = 0; nt < 4; nt++) {
                    int np = nt >> 1, j = (nt & 1) * 2;
                    mma16816(acc[mt][nt], aH[mt], bH[np][j], bH[np][j + 1]);
                }
            if (NT >= 2) {
#pragma unroll
                for (int mt = 0; mt < 4; mt++)
#pragma unroll
                    for (int nt = 0; nt < 4; nt++) {
                        int np = nt >> 1, j = (nt & 1) * 2;
                        mma16816(acc[mt][nt], aH[mt], bL[np][j], bL[np][j + 1]);
                    }
            }
            if (NT == 3) {
#pragma unroll
                for (int mt = 0; mt < 4; mt++)
#pragma unroll
                    for (int nt = 0; nt < 4; nt++) {
                        int np = nt >> 1, j = (nt & 1) * 2;
                        mma16816(acc[mt][nt], aL[mt], bH[np][j], bH[np][j + 1]);
                    }
            }
        }
        __syncthreads();
        if (ch + 2 < nch) load_stage(st, (ch + 2) * 32);
    }

    // ---- epilogue ----
#pragma unroll
    for (int mt = 0; mt < 4; mt++) {
#pragma unroll
        for (int nt = 0; nt < 4; nt++) {
            size_t row = m0 + wr * 64 + mt * 16 + (lane >> 2);
            int col = (int)n0 + wc * 32 + nt * 8 + (lane & 3) * 2;
            float b0 = bias ? __ldg(&bias[col])     : 0.f;
            float b1 = bias ? __ldg(&bias[col + 1]) : 0.f;
            float v00 = acc[mt][nt][0] + b0, v01 = acc[mt][nt][1] + b1;
            float v10 = acc[mt][nt][2] + b0, v11 = acc[mt][nt][3] + b1;
            if (relu) {
                v00 = fmaxf(v00, 0.f); v01 = fmaxf(v01, 0.f);
                v10 = fmaxf(v10, 0.f); v11 = fmaxf(v11, 0.f);
            }
            if (Cfp) {
                *(float2*)&Cfp[row * N + col]       = make_float2(v00, v01);
                *(float2*)&Cfp[(row + 8) * N + col] = make_float2(v10, v11);
            } else {
                __half2 p0 = __floats2half2_rn(v00, v01);
                __half2 p1 = __floats2half2_rn(v10, v11);
                *(uint32_t*)&Chf[row * N + col]       = *(uint32_t*)&p0;
                *(uint32_t*)&Chf[(row + 8) * N + col] = *(uint32_t*)&p1;
            }
        }
    }
}

// ================= assemble x1 for a PAIR of corners (reads hrterm once) =================
__global__ __launch_bounds__(256)
void k_asm2(const float* __restrict__ coord, const f16* __restrict__ hrterm,
            const f16* __restrict__ ccell, const float* __restrict__ w1,
            f16* __restrict__ x1, int pair)
{
    int bn = blockIdx.x;
    int b = bn >> 16;
    float cy0 = coord[(size_t)bn * 2 + 0];
    float cx0 = coord[(size_t)bn * 2 + 1];

    int c = threadIdx.x * 4;
    uint2 hraw = *(const uint2*)&hrterm[(size_t)bn * D1 + c];
    __half2 h01 = *(__half2*)&hraw.x, h23 = *(__half2*)&hraw.y;
    float4 h = make_float4(__low2float(h01), __high2float(h01),
                           __low2float(h23), __high2float(h23));
    float4 w0 = *(const float4*)&w1[(size_t)384 * D1 + c];
    float4 w8 = *(const float4*)&w1[(size_t)385 * D1 + c];

#pragma unroll
    for (int sub = 0; sub < 2; sub++) {
        int corner = pair * 2 + sub;
        float vx = (corner & 2) ? 1.f : -1.f;
        float vy = (corner & 1) ? 1.f : -1.f;
        float cy = cy0 + vx * (1.f / 64.f);
        float cx = cx0 + vy * (1.f / 64.f);
        int iy = (int)floorf((cy + 1.f) * 32.f);
        int ix = (int)floorf((cx + 1.f) * 32.f);
        bool valid = (iy >= 0) & (iy < LH) & (ix >= 0) & (ix < LW);
        float qy = valid ? (-1.f + (float)(2 * iy + 1) * (1.f / 64.f)) : 0.f;
        float qx = valid ? (-1.f + (float)(2 * ix + 1) * (1.f / 64.f)) : 0.f;
        float rely = (cy0 - qy) * 64.f;
        float relx = (cx0 - qx) * 64.f;

        float4 v;
        v.x = h.x + rely * w0.x + relx * w8.x;
        v.y = h.y + rely * w0.y + relx * w8.y;
        v.z = h.z + rely * w0.z + relx * w8.z;
        v.w = h.w + rely * w0.w + relx * w8.w;
        if (valid) {
            uint2 craw = *(const uint2*)&ccell[(size_t)(b * 4096 + iy * LW + ix) * D1 + c];
            __half2 c01 = *(__half2*)&craw.x, c23 = *(__half2*)&craw.y;
            v.x += __low2float(c01); v.y += __high2float(c01);
            v.z += __low2float(c23); v.w += __high2float(c23);
        }
        __half2 p0 = __floats2half2_rn(fmaxf(v.x, 0.f), fmaxf(v.y, 0.f));
        __half2 p1 = __floats2half2_rn(fmaxf(v.z, 0.f), fmaxf(v.w, 0.f));
        uint2 pk; pk.x = *(uint32_t*)&p0; pk.y = *(uint32_t*)&p1;
        *(uint2*)&x1[(size_t)(sub * BN_ + bn) * D1 + c] = pk;
    }
}

// ================= layer-5 + softmax reduce =================
__global__ __launch_bounds__(256)
void k_out(const float* __restrict__ h4, const float* __restrict__ w5,
           const float* __restrict__ b5, float* __restrict__ out)
{
    int gw = (blockIdx.x * blockDim.x + threadIdx.x) >> 5;
    int lane = threadIdx.x & 31;
    if (gw >= BN_) return;

    float pe[4], pw[4];
#pragma unroll
    for (int cnr = 0; cnr < 4; cnr++) {
        const float* h = h4 + (size_t)(cnr * BN_ + gw) * D4;
        float4 v = *(const float4*)&h[lane * 4];
        int k = lane * 4;
        float s0 = v.x * w5[(k+0)*2+0] + v.y * w5[(k+1)*2+0] + v.z * w5[(k+2)*2+0] + v.w * w5[(k+3)*2+0];
        float s1 = v.x * w5[(k+0)*2+1] + v.y * w5[(k+1)*2+1] + v.z * w5[(k+2)*2+1] + v.w * w5[(k+3)*2+1];
#pragma unroll
        for (int o = 16; o; o >>= 1) {
            s0 += __shfl_xor_sync(0xffffffffu, s0, o);
            s1 += __shfl_xor_sync(0xffffffffu, s1, o);
        }
        pe[cnr] = s0 + b5[0];
        pw[cnr] = s1 + b5[1];
    }
    if (lane == 0) {
        float m = fmaxf(fmaxf(pw[0], pw[1]), fmaxf(pw[2], pw[3]));
        float e0 = expf(pw[0] - m), e1 = expf(pw[1] - m);
        float e2 = expf(pw[2] - m), e3 = expf(pw[3] - m);
        float se = e0 + e1 + e2 + e3;
        out[gw] = (pe[0]*e0 + pe[1]*e1 + pe[2]*e2 + pe[3]*e3) / se;
    }
}

// ================= launch =================
extern "C" void kernel_launch(void* const* d_in, const int* in_sizes, int n_in,
                              void* d_out, int out_size)
{
    const float* feat  = (const float*)d_in[0];
    const float* coord = (const float*)d_in[1];
    const float* hrg   = (const float*)d_in[2];
    const float* lrg   = (const float*)d_in[3];
    const float* w1 = (const float*)d_in[4];  const float* b1 = (const float*)d_in[5];
    const float* w2 = (const float*)d_in[6];  const float* b2 = (const float*)d_in[7];
    const float* w3 = (const float*)d_in[8];  const float* b3 = (const float*)d_in[9];
    const float* w4 = (const float*)d_in[10]; const float* b4 = (const float*)d_in[11];
    const float* w5 = (const float*)d_in[12]; const float* b5 = (const float*)d_in[13];
    float* out = (float*)d_out;

    unsigned char* S;
    cudaGetSymbolAddress((void**)&S, g_scratch);
    f16*   qhrH  = (f16*)(S + O_QHR_HI);   f16* qhrL  = (f16*)(S + O_QHR_LO);
    f16*   celH  = (f16*)(S + O_CEL_HI);   f16* celL  = (f16*)(S + O_CEL_LO);
    float* whrF  = (float*)(S + O_WHR_F);  float* wcellF = (float*)(S + O_WCELL_F);
    f16*   whrtH = (f16*)(S + O_WHRT_H);   f16* whrtL = (f16*)(S + O_WHRT_L);
    f16*   wctH  = (f16*)(S + O_WCT_H);    f16* wctL  = (f16*)(S + O_WCT_L);
    f16*   w2tH  = (f16*)(S + O_W2T_H);
    f16*   w3tH  = (f16*)(S + O_W3T_H);    f16* w3tL  = (f16*)(S + O_W3T_L);
    f16*   w4tH  = (f16*)(S + O_W4T_H);    f16* w4tL  = (f16*)(S + O_W4T_L);
    f16*   hrterm = (f16*)(S + O_HRTERM);
    f16*   ccell  = (f16*)(S + O_CCELL);
    f16*   x1 = (f16*)(S + O_X1);
    f16*   h2 = (f16*)(S + O_H2);
    f16*   h3 = (f16*)(S + O_H3);
    float* h4 = (float*)(S + O_H4);

    const int SMEM3 = 2 * 4 * TILE_BYTES;   // 81920 (occ 1)
    const int SMEM2 = 2 * 3 * TILE_BYTES;   // 61440 (x2 CTAs = 120KB/SM)
    const int SMEM1 = 2 * 2 * TILE_BYTES;   // 40960 (x2 CTAs = 80KB/SM)
    cudaFuncSetAttribute(k_gemm<3>, cudaFuncAttributeMaxDynamicSharedMemorySize, SMEM3);
    cudaFuncSetAttribute(k_gemm<2>, cudaFuncAttributeMaxDynamicSharedMemorySize, SMEM2);
    cudaFuncSetAttribute(k_gemm<1>, cudaFuncAttributeMaxDynamicSharedMemorySize, SMEM1);

    dim3 t32x8(32, 8);
    k_tsplit<<<dim3(NPIX/32, CFEAT/32, Bsz), t32x8>>>(hrg, qhrH, qhrL, NPIX, 128, 0, 1.f,
        (size_t)CFEAT * NPIX, (size_t)NPIX * 128);
    k_tsplit<<<dim3(4096/32, CFEAT/32, Bsz), t32x8>>>(feat, celH, celL, 4096, 256, 0, 1.f,
        (size_t)CFEAT * 4096, (size_t)4096 * 256);
    k_tsplit<<<dim3(4096/32, CFEAT/32, Bsz), t32x8>>>(lrg, celH, celL, 4096, 256, 128, -1.f,
        (size_t)CFEAT * 4096, (size_t)4096 * 256);
    k_prepw<<<(384 * D1 + 255) / 256, 256>>>(w1, whrF, wcellF);
    k_wsplit<<<dim3(D1/32, 128/32), t32x8>>>(whrF,   whrtH, whrtL, 128, D1);
    k_wsplit<<<dim3(D1/32, 256/32), t32x8>>>(wcellF, wctH,  wctL,  256, D1);
    k_wsplit<<<dim3(D2/32, D1/32),  t32x8>>>(w2, w2tH, nullptr, D1, D2);
    k_wsplit<<<dim3(D3/32, D2/32),  t32x8>>>(w3, w3tH, w3tL, D2, D3);
    k_wsplit<<<dim3(D4/32, D3/32),  t32x8>>>(w4, w4tH, w4tL, D3, D4);

    // HR term: [131072,128]@[128,1024] + b1 -> f16 (3-term)
    k_gemm<3><<<dim3(D1/128, BN_/128), 256, SMEM3>>>(qhrH, qhrL, whrtH, whrtL, b1,
        nullptr, hrterm, D1, 128, 0);
    // cell term: [8192,256]@[256,1024] -> f16 (3-term)
    k_gemm<3><<<dim3(D1/128, NCELL/128), 256, SMEM3>>>(celH, celL, wctH, wctL, nullptr,
        nullptr, ccell, D1, 256, 0);

    const int M2 = 2 * BN_;   // two corners per chain
    for (int pair = 0; pair < 2; pair++) {
        k_asm2<<<BN_, 256>>>(coord, hrterm, ccell, w1, x1, pair);
        // layer 2: 1-term (Ah*Bh)
        k_gemm<1><<<dim3(D2/128, M2/128), 256, SMEM1>>>(x1, nullptr, w2tH, nullptr, b2,
            nullptr, h2, D2, D1, 1);
        // layer 3: 2-term (Ah*Bh + Ah*Bl)
        k_gemm<2><<<dim3(D3/128, M2/128), 256, SMEM2>>>(h2, nullptr, w3tH, w3tL, b3,
            nullptr, h3, D3, D2, 1);
        // layer 4: 2-term
        k_gemm<2><<<dim3(D4/128, M2/128), 256, SMEM2>>>(h3, nullptr, w4tH, w4tL, b4,
            h4 + (size_t)pair * 2 * BN_ * D4, nullptr, D4, D3, 1);
    }

    k_out<<<(BN_ * 32) / 256, 256>>>(h4, w5, b5, out);
}